// round 1
// baseline (speedup 1.0000x reference)
#include <cuda_runtime.h>
#include <math.h>

#define Bsz 256
#define Hsz 512
#define Isz 512

// ---------------- scratch (device globals, no allocation) ----------------
__device__ float g_partial[4 * 4 * Bsz * Hsz]; // [z][gate][b][k] GEMM K-split partials (8 MB)
__device__ float g_hbp[4 * Bsz * Hsz];         // [z][b][k] hebb-dot h-split partials (2 MB)
__device__ float g_itc[Bsz * Hsz];             // inputstocell
__device__ float g_eta[Bsz];                   // tanh(hactiv @ Wmod.T + bmod)

// ---------------------------------------------------------------------------
// Kernel 1: fused gate GEMMs.
// For each (b,k) computes partial sums over a K-split (z = blockIdx.z, 128 of 512):
//   g=0: x·Wxf[k,:] + h0·Whf[k,:]
//   g=1: x·Wxi[k,:] + h0·Whi[k,:]
//   g=2: x·Wxo[k,:] + h0·Who[k,:]
//   g=3: x·Wxc[k,:] + h0·w[:,k]     (plastic-weight dense part)
// Block tile 64(b) x 64(k), BK=16, 256 threads, 4x4 microtile per gate.
// ---------------------------------------------------------------------------
__global__ __launch_bounds__(256) void gates_gemm(
    const float* __restrict__ x, const float* __restrict__ h0,
    const float* __restrict__ Wxf, const float* __restrict__ Wxi,
    const float* __restrict__ Wxo, const float* __restrict__ Wxc,
    const float* __restrict__ Whf, const float* __restrict__ Whi,
    const float* __restrict__ Who, const float* __restrict__ w)
{
    __shared__ float sA[2][16][68];  // [x|h][kk][m], pad 68 keeps float4 aligned + conflict-free
    __shared__ float sB[8][16][68];  // 0..3: Wxf,Wxi,Wxo,Wxc ; 4..6: Whf,Whi,Who ; 7: w

    const int tid = threadIdx.x;
    const int m0 = blockIdx.y * 64;
    const int n0 = blockIdx.x * 64;
    const int kbase = blockIdx.z * 128;
    const int ty = tid >> 4, tx = tid & 15;

    float acc[4][16];
#pragma unroll
    for (int g = 0; g < 4; g++)
#pragma unroll
        for (int i = 0; i < 16; i++) acc[g][i] = 0.f;

    const float* Wt[7] = {Wxf, Wxi, Wxo, Wxc, Whf, Whi, Who};

    for (int kc = 0; kc < 128; kc += 16) {
        const int kk0 = kbase + kc;
        const int lk = tid & 15, lr = tid >> 4;
#pragma unroll
        for (int i = 0; i < 4; i++) {
            int m = lr + i * 16;
            sA[0][lk][m] = x[(m0 + m) * Isz + kk0 + lk];
            sA[1][lk][m] = h0[(m0 + m) * Hsz + kk0 + lk];
        }
#pragma unroll
        for (int j = 0; j < 7; j++) {
            const float* Wp = Wt[j];
#pragma unroll
            for (int i = 0; i < 4; i++) {
                int n = lr + i * 16;
                sB[j][lk][n] = Wp[(n0 + n) * Hsz + kk0 + lk]; // I==H==512 stride
            }
        }
        {
            const int ln = tid & 63, lz = tid >> 6;
#pragma unroll
            for (int i = 0; i < 4; i++) {
                int kk = lz + i * 4;
                sB[7][kk][ln] = w[(kk0 + kk) * Hsz + n0 + ln]; // w accessed [h][k]
            }
        }
        __syncthreads();

#pragma unroll
        for (int kk = 0; kk < 16; kk++) {
            const float4 ax4 = *(const float4*)&sA[0][kk][ty * 4];
            const float4 ah4 = *(const float4*)&sA[1][kk][ty * 4];
            const float ax[4] = {ax4.x, ax4.y, ax4.z, ax4.w};
            const float ah[4] = {ah4.x, ah4.y, ah4.z, ah4.w};
#pragma unroll
            for (int g = 0; g < 4; g++) {
                const float4 bx4 = *(const float4*)&sB[g][kk][tx * 4];
                const float4 bh4 = *(const float4*)&sB[(g < 3) ? (4 + g) : 7][kk][tx * 4];
                const float bx[4] = {bx4.x, bx4.y, bx4.z, bx4.w};
                const float bh[4] = {bh4.x, bh4.y, bh4.z, bh4.w};
#pragma unroll
                for (int mi = 0; mi < 4; mi++)
#pragma unroll
                    for (int ni = 0; ni < 4; ni++)
                        acc[g][mi * 4 + ni] += ax[mi] * bx[ni] + ah[mi] * bh[ni];
            }
        }
        __syncthreads();
    }

    const int z = blockIdx.z;
#pragma unroll
    for (int g = 0; g < 4; g++)
#pragma unroll
        for (int mi = 0; mi < 4; mi++) {
            int m = m0 + ty * 4 + mi, n = n0 + tx * 4;
            float4 v = {acc[g][mi * 4 + 0], acc[g][mi * 4 + 1],
                        acc[g][mi * 4 + 2], acc[g][mi * 4 + 3]};
            *(float4*)&g_partial[(((z * 4 + g) * Bsz) + m) * Hsz + n] = v;
        }
}

// ---------------------------------------------------------------------------
// Kernel 2: per-sample plastic contraction partials.
//   g_hbp[z][b][k] = sum_{h in z-slab} h0[b,h] * hebb[b,h,k]
// grid (4, 256), 128 threads; each thread owns 4 consecutive k (float4).
// Streams hebb exactly once (268 MB), fully coalesced.
// ---------------------------------------------------------------------------
__global__ __launch_bounds__(128) void hebbdot(
    const float* __restrict__ h0, const float* __restrict__ hebb)
{
    const int b = blockIdx.y, hz = blockIdx.x, t = threadIdx.x;
    __shared__ float sh[128];
    sh[t] = h0[b * Hsz + hz * 128 + t];
    __syncthreads();

    const float4* hp = (const float4*)(hebb + (size_t)b * Hsz * Hsz + (size_t)(hz * 128) * Hsz) + t;
    float4 acc = {0.f, 0.f, 0.f, 0.f};
#pragma unroll 8
    for (int h = 0; h < 128; h++) {
        const float4 v = hp[(size_t)h * 128];
        const float s = sh[h];
        acc.x += s * v.x; acc.y += s * v.y; acc.z += s * v.z; acc.w += s * v.w;
    }
    ((float4*)(g_hbp + (hz * Bsz + b) * Hsz))[t] = acc;
}

// ---------------------------------------------------------------------------
// Kernel 3: combine partials, gate nonlinearities, cell/hactiv outputs,
// inputstocell scratch, and block-wide reduction for the neuromodulator eta.
// grid 256 (one block per batch row), 512 threads (one per k).
// ---------------------------------------------------------------------------
__global__ __launch_bounds__(512) void combine(
    const float* __restrict__ c0, const float* __restrict__ alpha,
    const float* __restrict__ bxf, const float* __restrict__ bhf,
    const float* __restrict__ bxi, const float* __restrict__ bhi,
    const float* __restrict__ bxo, const float* __restrict__ bho,
    const float* __restrict__ bxc,
    const float* __restrict__ Wmod, const float* __restrict__ bmod,
    float* __restrict__ out_h, float* __restrict__ out_c)
{
    const int b = blockIdx.x, k = threadIdx.x;

    float p[4];
#pragma unroll
    for (int g = 0; g < 4; g++) {
        float s = 0.f;
#pragma unroll
        for (int z = 0; z < 4; z++) s += g_partial[(((z * 4 + g) * Bsz) + b) * Hsz + k];
        p[g] = s;
    }
    float hbs = 0.f;
#pragma unroll
    for (int z = 0; z < 4; z++) hbs += g_hbp[(z * Bsz + b) * Hsz + k];

    const float fgt = 1.f / (1.f + expf(-(p[0] + bxf[k] + bhf[k])));
    const float ipt = 1.f / (1.f + expf(-(p[1] + bxi[k] + bhi[k])));
    const float opt = 1.f / (1.f + expf(-(p[2] + bxo[k] + bho[k])));
    const float itc = tanhf(p[3] + bxc[k] + alpha[k] * hbs);
    const float cell = fgt * c0[b * Hsz + k] + ipt * itc;
    const float hact = opt * tanhf(cell);

    out_h[b * Hsz + k] = hact;
    out_c[b * Hsz + k] = cell;
    g_itc[b * Hsz + k] = itc;

    // eta[b] = tanh( sum_k hact*Wmod[k] + bmod )
    float v = hact * Wmod[k];
#pragma unroll
    for (int off = 16; off; off >>= 1) v += __shfl_xor_sync(0xffffffffu, v, off);
    __shared__ float sred[16];
    const int lane = k & 31, wid = k >> 5;
    if (lane == 0) sred[wid] = v;
    __syncthreads();
    if (wid == 0) {
        float t = (lane < 16) ? sred[lane] : 0.f;
#pragma unroll
        for (int off = 8; off; off >>= 1) t += __shfl_xor_sync(0xffffffffu, t, off);
        if (lane == 0) g_eta[b] = tanhf(t + bmod[0]);
    }
}

// ---------------------------------------------------------------------------
// Kernel 4: Hebbian trace update (dominant memory cost: 268 MB read + 268 MB write).
//   hebb_new[b,h,k] = clip(hebb[b,h,k] + (eta[b]*Wfan[k]+bfan[k])*itc[b,k] * h0[b,h], +-2)
// grid (16, 256): 32 h-rows per block, 128 threads x float4 over k.
// ---------------------------------------------------------------------------
__global__ __launch_bounds__(128) void hebbupd(
    const float* __restrict__ h0, const float* __restrict__ hebb,
    const float* __restrict__ Wfan, const float* __restrict__ bfan,
    float* __restrict__ out_hebb)
{
    const int b = blockIdx.y, hb0 = blockIdx.x * 32, t = threadIdx.x;
    __shared__ float4 s[128];
    __shared__ float sh0[32];

    const float eta = g_eta[b];
    {
        const int k = t * 4;
        const float4 it = *(const float4*)&g_itc[b * Hsz + k];
        float4 sv;
        sv.x = (eta * Wfan[k + 0] + bfan[k + 0]) * it.x;
        sv.y = (eta * Wfan[k + 1] + bfan[k + 1]) * it.y;
        sv.z = (eta * Wfan[k + 2] + bfan[k + 2]) * it.z;
        sv.w = (eta * Wfan[k + 3] + bfan[k + 3]) * it.w;
        s[t] = sv;
    }
    if (t < 32) sh0[t] = h0[b * Hsz + hb0 + t];
    __syncthreads();

    const float4 sk = s[t];
    const float4* hp = (const float4*)(hebb + (size_t)b * Hsz * Hsz + (size_t)hb0 * Hsz) + t;
    float4* op = (float4*)(out_hebb + (size_t)b * Hsz * Hsz + (size_t)hb0 * Hsz) + t;
#pragma unroll 4
    for (int hh = 0; hh < 32; hh++) {
        float4 v = hp[(size_t)hh * 128];
        const float hv = sh0[hh];
        v.x = fminf(fmaxf(v.x + hv * sk.x, -2.f), 2.f);
        v.y = fminf(fmaxf(v.y + hv * sk.y, -2.f), 2.f);
        v.z = fminf(fmaxf(v.z + hv * sk.z, -2.f), 2.f);
        v.w = fminf(fmaxf(v.w + hv * sk.w, -2.f), 2.f);
        op[(size_t)hh * 128] = v;
    }
}

// ---------------------------------------------------------------------------
extern "C" void kernel_launch(void* const* d_in, const int* in_sizes, int n_in,
                              void* d_out, int out_size)
{
    const float* x     = (const float*)d_in[0];
    const float* h0    = (const float*)d_in[1];
    const float* c0    = (const float*)d_in[2];
    const float* hebb  = (const float*)d_in[3];
    const float* w     = (const float*)d_in[4];
    const float* alpha = (const float*)d_in[5];
    const float* Wxf   = (const float*)d_in[6];
    const float* bxf   = (const float*)d_in[7];
    const float* Whf   = (const float*)d_in[8];
    const float* bhf   = (const float*)d_in[9];
    const float* Wxi   = (const float*)d_in[10];
    const float* bxi   = (const float*)d_in[11];
    const float* Whi   = (const float*)d_in[12];
    const float* bhi   = (const float*)d_in[13];
    const float* Wxo   = (const float*)d_in[14];
    const float* bxo   = (const float*)d_in[15];
    const float* Who   = (const float*)d_in[16];
    const float* bho   = (const float*)d_in[17];
    const float* Wxc   = (const float*)d_in[18];
    const float* bxc   = (const float*)d_in[19];
    const float* Wmod  = (const float*)d_in[20];
    const float* bmod  = (const float*)d_in[21];
    const float* Wfan  = (const float*)d_in[22];
    const float* bfan  = (const float*)d_in[23];

    float* out = (float*)d_out;
    float* out_h    = out;                     // hactiv [256,512]
    float* out_c    = out + Bsz * Hsz;         // cell   [256,512]
    float* out_hebb = out + 2 * Bsz * Hsz;     // hebb_new [256,512,512]

    gates_gemm<<<dim3(8, 4, 4), 256>>>(x, h0, Wxf, Wxi, Wxo, Wxc, Whf, Whi, Who, w);
    hebbdot<<<dim3(4, 256), 128>>>(h0, hebb);
    combine<<<256, 512>>>(c0, alpha, bxf, bhf, bxi, bhi, bxo, bho, bxc, Wmod, bmod,
                          out_h, out_c);
    hebbupd<<<dim3(16, 256), 128>>>(h0, hebb, Wfan, bfan, out_hebb);
}